// round 6
// baseline (speedup 1.0000x reference)
#include <cuda_runtime.h>
#include <cuda_fp16.h>

#define NN 320
#define DD 64

// Precomputed, perm-independent state (static device globals: no allocation).
__device__ __align__(16) __half d_Dlh[NN*NN]; // Delta = ||x_a+x_b|| - ||x_a-x_b||
__device__ __align__(16) __half d_Dph[NN*NN]; // ||x_a - x_b||
__device__ float d_RD[NN];      // row sums of Delta (fp32)
__device__ float d_rowC[NN];    // per-row sum of Dp over b>a (fp32)
__device__ float d_sn[NN];      // squared norms
__device__ float d_qd[NN];      // X1 . x_a = row sum of Gram

__device__ __forceinline__ float warpRed(float v){
#pragma unroll
    for (int o = 16; o > 0; o >>= 1) v += __shfl_down_sync(0xffffffffu, v, o);
    return v;
}

// Fused precompute: one block per row a, thread = column b.
__global__ void __launch_bounds__(NN) k_pre(const float* __restrict__ x){
    __shared__ float xa[DD];
    __shared__ float sa_sh;
    __shared__ float red[3][10];
    int a = blockIdx.x, b = threadIdx.x;
    if (b < DD) xa[b] = x[a*DD + b];
    __syncthreads();
    const float4* xb = reinterpret_cast<const float4*>(x + b*DD);
    float g = 0.f, nb = 0.f;
#pragma unroll
    for (int i = 0; i < DD/4; i++){
        float4 v = xb[i];
        g  += xa[4*i]*v.x + xa[4*i+1]*v.y + xa[4*i+2]*v.z + xa[4*i+3]*v.w;
        nb += v.x*v.x + v.y*v.y + v.z*v.z + v.w*v.w;
    }
    if (b == a){ sa_sh = nb; d_sn[a] = nb; }
    __syncthreads();
    float sa = sa_sh;
    float dp = sqrtf(fmaxf(sa + nb - 2.f*g, 0.f));
    float dm = sqrtf(fmaxf(sa + nb + 2.f*g, 0.f));
    float dl = dm - dp;
    d_Dlh[a*NN + b] = __float2half_rn(dl);
    d_Dph[a*NN + b] = __float2half_rn(dp);

    int w = b >> 5, l = b & 31;
    float v0 = warpRed(dl);
    float v1 = warpRed(b > a ? dp : 0.f);
    float v2 = warpRed(g);
    if (l == 0){ red[0][w] = v0; red[1][w] = v1; red[2][w] = v2; }
    __syncthreads();
    if (b == 0){
        float s0 = 0.f, s1 = 0.f, s2 = 0.f;
#pragma unroll
        for (int i = 0; i < 10; i++){ s0 += red[0][i]; s1 += red[1][i]; s2 += red[2][i]; }
        d_RD[a]   = s0;   // row sum of Delta
        d_rowC[a] = s1;   // row sum of Dp over b>a
        d_qd[a]   = s2;   // X1 . x_a
    }
}

// Main: one block per dataset. 320 threads = 40 oct-columns x 8 row-slices.
// uint4 half gathers, HADD2 accumulation, fp32 flush to shared.
__global__ void __launch_bounds__(NN, 5) k_main(const float* __restrict__ x,
                                                const int* __restrict__ ptype,
                                                const int* __restrict__ perms,
                                                float* __restrict__ out){
    __shared__ float beta[NN], chi[NN];
    __shared__ int   Bl[NN], Cl[NN];
    __shared__ int   offB[10], offC[10], cnt[2];
    __shared__ float4 sB4[8*NN/4];     // Delta col partials: [slice][oct-col]
    __shared__ float4 sX4[8*NN/4];     // Dp col partials
    __shared__ float zp[NN];
    __shared__ float red[9][10];

    int t = threadIdx.x, p = blockIdx.x;
    int w = t >> 5, l = t & 31;

    beta[t] = 0.f; chi[t] = 0.f;
    __syncthreads();

    int a  = (p == 0) ? t : perms[(p-1)*NN + t];
    int fn = (ptype[t] == 0);
    int fa = (ptype[a] == 0);
    int u  = (a != t) && fn && fa;          // this position's row is negated
    if (fn) chi[a]  = 1.f;                  // image of a fermion position
    if (u)  beta[a] = 1.f;                  // image of a negated position

    // Deterministic warp-ballot compaction into index lists
    unsigned ballB = __ballot_sync(0xffffffffu, u);
    unsigned ballC = __ballot_sync(0xffffffffu, fn);
    if (l == 0){ offB[w] = __popc(ballB); offC[w] = __popc(ballC); }
    __syncthreads();
    if (t == 0){
        int sB = 0, sC = 0;
#pragma unroll
        for (int i = 0; i < 10; i++){
            int bb = offB[i]; offB[i] = sB; sB += bb;
            int cc = offC[i]; offC[i] = sC; sC += cc;
        }
        cnt[0] = sB; cnt[1] = sC;
    }
    __syncthreads();
    unsigned lt = (1u << l) - 1u;
    if (u)  Bl[offB[w] + __popc(ballB & lt)] = a;
    if (fn) Cl[offC[w] + __popc(ballC & lt)] = a;
    __syncthreads();
    int Bc = cnt[0], Cc = cnt[1];

    int s8 = t / 40;          // 0..7 row slice
    int q8 = t - s8*40;       // 0..39 oct-column
    const __half* pDl = d_Dlh + 8*q8;
    const __half* pDp = d_Dph + 8*q8;
    const __half2 hz = __float2half2_rn(0.f);
    int sidx = s8*(NN/4) + 2*q8;

    // B loop: Delta rows (|B| ~ 80 -> <=12 iters/thread, safe in half)
    {
        __half2 c0 = hz, c1 = hz, c2 = hz, c3 = hz;
        for (int i = s8; i < Bc; i += 8){
            int r = Bl[i] * NN;
            uint4 uv = *reinterpret_cast<const uint4*>(pDl + r);
            c0 = __hadd2(c0, *reinterpret_cast<__half2*>(&uv.x));
            c1 = __hadd2(c1, *reinterpret_cast<__half2*>(&uv.y));
            c2 = __hadd2(c2, *reinterpret_cast<__half2*>(&uv.z));
            c3 = __hadd2(c3, *reinterpret_cast<__half2*>(&uv.w));
        }
        float2 f0 = __half22float2(c0), f1 = __half22float2(c1),
               f2 = __half22float2(c2), f3 = __half22float2(c3);
        sB4[sidx]   = make_float4(f0.x, f0.y, f1.x, f1.y);
        sB4[sidx+1] = make_float4(f2.x, f2.y, f3.x, f3.y);
    }

    // C loop: Dp rows (|C| ~ 160 -> <=22 iters), chunked flush to shared
    {
        sX4[sidx]   = make_float4(0.f,0.f,0.f,0.f);
        sX4[sidx+1] = make_float4(0.f,0.f,0.f,0.f);
        __half2 d0 = hz, d1 = hz, d2 = hz, d3 = hz;
        int k = 0;
        for (int i = s8; i < Cc; i += 8){
            int r = Cl[i] * NN;
            uint4 uv = *reinterpret_cast<const uint4*>(pDp + r);
            d0 = __hadd2(d0, *reinterpret_cast<__half2*>(&uv.x));
            d1 = __hadd2(d1, *reinterpret_cast<__half2*>(&uv.y));
            d2 = __hadd2(d2, *reinterpret_cast<__half2*>(&uv.z));
            d3 = __hadd2(d3, *reinterpret_cast<__half2*>(&uv.w));
            if (++k == 11){
                float2 f0 = __half22float2(d0), f1 = __half22float2(d1),
                       f2 = __half22float2(d2), f3 = __half22float2(d3);
                float4 v0 = sX4[sidx], v1 = sX4[sidx+1];
                v0.x += f0.x; v0.y += f0.y; v0.z += f1.x; v0.w += f1.y;
                v1.x += f2.x; v1.y += f2.y; v1.z += f3.x; v1.w += f3.y;
                sX4[sidx] = v0; sX4[sidx+1] = v1;
                d0 = hz; d1 = hz; d2 = hz; d3 = hz; k = 0;
            }
        }
        float2 f0 = __half22float2(d0), f1 = __half22float2(d1),
               f2 = __half22float2(d2), f3 = __half22float2(d3);
        float4 v0 = sX4[sidx], v1 = sX4[sidx+1];
        v0.x += f0.x; v0.y += f0.y; v0.z += f1.x; v0.w += f1.y;
        v1.x += f2.x; v1.y += f2.y; v1.z += f3.x; v1.w += f3.y;
        sX4[sidx] = v0; sX4[sidx+1] = v1;
    }

    // s = sum_{a in B} x_a (fp32 exact): GG = ||s||^2 = beta^T G beta
    {
        int dd = t & 63, g5 = t >> 6;   // 5 row-slices of 64 dims
        float sacc = 0.f;
        for (int i = g5; i < Bc; i += 5) sacc += x[Bl[i]*DD + dd];
        zp[t] = sacc;
    }
    __syncthreads();

    // Per-column totals (thread t = column t)
    const float* fB = reinterpret_cast<const float*>(sB4);
    const float* fX = reinterpret_cast<const float*>(sX4);
    float colB = 0.f, colX = 0.f;
#pragma unroll
    for (int s = 0; s < 8; s++){ colB += fB[s*NN + t]; colX += fX[s*NN + t]; }

    float z2p = 0.f;
    if (t < 64){
        float z = zp[t] + zp[64+t] + zp[128+t] + zp[192+t] + zp[256+t];
        z2p = z*z;
    }

    float myb = beta[t], myc = chi[t];
    float vBB  = myb * colB;                       // beta^T Delta beta
    float vBX  = myc * colB;                       // chi^T Delta beta
    float vXX  = myc * colX;                       // chi^T Dp chi
    float vLin = (t < Bc) ? d_RD[Bl[t]] : 0.f;     // beta^T RDelta
    float vQ   = (t < Bc) ? d_qd[Bl[t]] : 0.f;     // X1 . sum_B x

    float r0 = warpRed(vBB), r1 = warpRed(z2p), r2 = warpRed(vBX),
          r3 = warpRed(vXX), r4 = warpRed(vLin), r5 = warpRed(vQ),
          r6 = warpRed(d_rowC[t]),                 // -> C_Dp
          r7 = warpRed(d_sn[t]),                   // -> S1
          r8 = warpRed(d_qd[t]);                   // -> ||X1||^2
    if (l == 0){ red[0][w]=r0; red[1][w]=r1; red[2][w]=r2;
                 red[3][w]=r3; red[4][w]=r4; red[5][w]=r5;
                 red[6][w]=r6; red[7][w]=r7; red[8][w]=r8; }
    __syncthreads();
    if (t == 0){
        float BB=0.f, GG=0.f, BX=0.f, XX=0.f, LIN=0.f, QS=0.f,
              CDP=0.f, S1=0.f, X1SQ=0.f;
#pragma unroll
        for (int i = 0; i < 10; i++){
            BB += red[0][i]; GG += red[1][i]; BX += red[2][i];
            XX += red[3][i]; LIN += red[4][i]; QS += red[5][i];
            CDP += red[6][i]; S1 += red[7][i]; X1SQ += red[8][i];
        }
        const float M = 51040.f;                    // 320*319/2
        float Sv  = CDP + LIN + BB - 2.f*BX - XX;
        float Z2  = X1SQ - 4.f*QS + 4.f*GG;         // ||X1 - 2 sum_B x||^2
        float Sv2 = 320.f * S1 - Z2;
        out[p] = (Sv2 - Sv*Sv/M) / (M - 1.f);
    }
}

extern "C" void kernel_launch(void* const* d_in, const int* in_sizes, int n_in,
                              void* d_out, int out_size){
    const float* data  = (const float*)d_in[0];
    const int*   ptype = (const int*)d_in[3];
    const int*   perms = (const int*)d_in[4];
    float* out = (float*)d_out;
    k_pre <<<NN,   NN>>>(data);
    k_main<<<1001, NN>>>(data, ptype, perms, out);
}

// round 7
// speedup vs baseline: 1.0682x; 1.0682x over previous
#include <cuda_runtime.h>
#include <cuda_fp16.h>

#define NN 320
#define DD 64

// Precomputed, perm-independent state (static device globals: no allocation).
__device__ __align__(16) __half d_Dlh[NN*NN]; // Delta = ||x_a+x_b|| - ||x_a-x_b||
__device__ __align__(16) __half d_Dph[NN*NN]; // ||x_a - x_b||
__device__ float d_RD[NN];      // row sums of Delta (fp32)
__device__ float d_rowC[NN];    // per-row sum of Dp over b>a (fp32)
__device__ float d_sn[NN];      // squared norms
__device__ float d_qd[NN];      // X1 . x_a = row sum of Gram

__device__ __forceinline__ float warpRed(float v){
#pragma unroll
    for (int o = 16; o > 0; o >>= 1) v += __shfl_down_sync(0xffffffffu, v, o);
    return v;
}

// Fused precompute: one block per row a, thread = column b.
__global__ void __launch_bounds__(NN) k_pre(const float* __restrict__ x){
    __shared__ float xa[DD];
    __shared__ float sa_sh;
    __shared__ float red[3][10];
    int a = blockIdx.x, b = threadIdx.x;
    if (b < DD) xa[b] = x[a*DD + b];
    __syncthreads();
    const float4* xb = reinterpret_cast<const float4*>(x + b*DD);
    float g = 0.f, nb = 0.f;
#pragma unroll
    for (int i = 0; i < DD/4; i++){
        float4 v = xb[i];
        g  += xa[4*i]*v.x + xa[4*i+1]*v.y + xa[4*i+2]*v.z + xa[4*i+3]*v.w;
        nb += v.x*v.x + v.y*v.y + v.z*v.z + v.w*v.w;
    }
    if (b == a){ sa_sh = nb; d_sn[a] = nb; }
    __syncthreads();
    float sa = sa_sh;
    float dp = sqrtf(fmaxf(sa + nb - 2.f*g, 0.f));
    float dm = sqrtf(fmaxf(sa + nb + 2.f*g, 0.f));
    float dl = dm - dp;
    d_Dlh[a*NN + b] = __float2half_rn(dl);
    d_Dph[a*NN + b] = __float2half_rn(dp);

    int w = b >> 5, l = b & 31;
    float v0 = warpRed(dl);
    float v1 = warpRed(b > a ? dp : 0.f);
    float v2 = warpRed(g);
    if (l == 0){ red[0][w] = v0; red[1][w] = v1; red[2][w] = v2; }
    __syncthreads();
    if (b == 0){
        float s0 = 0.f, s1 = 0.f, s2 = 0.f;
#pragma unroll
        for (int i = 0; i < 10; i++){ s0 += red[0][i]; s1 += red[1][i]; s2 += red[2][i]; }
        d_RD[a]   = s0;   // row sum of Delta
        d_rowC[a] = s1;   // row sum of Dp over b>a
        d_qd[a]   = s2;   // X1 . x_a
    }
}

// Main: one block per dataset. 320 threads = 4 row-slices x 80 quad-columns.
// uint2 half gathers, HADD2 accumulation, register fp32 promotion.
__global__ void __launch_bounds__(NN, 6) k_main(const float* __restrict__ x,
                                                const int* __restrict__ ptype,
                                                const int* __restrict__ perms,
                                                float* __restrict__ out){
    __shared__ float beta[NN], chi[NN];
    __shared__ int   Bl[NN], Cl[NN];
    __shared__ int   offB[10], offC[10], cnt[2];
    __shared__ float4 sB4[4][NN/4];     // Delta col partials [slice][quad-col]
    __shared__ float4 sX4[4][NN/4];     // Dp col partials
    __shared__ float zp[NN];
    __shared__ float red[9][10];

    int t = threadIdx.x, p = blockIdx.x;
    int w = t >> 5, l = t & 31;

    beta[t] = 0.f; chi[t] = 0.f;
    __syncthreads();

    int a  = (p == 0) ? t : perms[(p-1)*NN + t];
    int fn = (ptype[t] == 0);
    int fa = (ptype[a] == 0);
    int u  = (a != t) && fn && fa;          // this position's row is negated
    if (fn) chi[a]  = 1.f;                  // image of a fermion position
    if (u)  beta[a] = 1.f;                  // image of a negated position

    // Deterministic warp-ballot compaction into index lists
    unsigned ballB = __ballot_sync(0xffffffffu, u);
    unsigned ballC = __ballot_sync(0xffffffffu, fn);
    if (l == 0){ offB[w] = __popc(ballB); offC[w] = __popc(ballC); }
    __syncthreads();
    if (t == 0){
        int sB = 0, sC = 0;
#pragma unroll
        for (int i = 0; i < 10; i++){
            int bb = offB[i]; offB[i] = sB; sB += bb;
            int cc = offC[i]; offC[i] = sC; sC += cc;
        }
        cnt[0] = sB; cnt[1] = sC;
    }
    __syncthreads();
    unsigned lt = (1u << l) - 1u;
    if (u)  Bl[offB[w] + __popc(ballB & lt)] = a;
    if (fn) Cl[offC[w] + __popc(ballC & lt)] = a;
    __syncthreads();
    int Bc = cnt[0], Cc = cnt[1];

    int s = t / 80;           // 0..3 row slice
    int q = t - s*80;         // 0..79 quad-column
    const __half* pDl = d_Dlh + 4*q;
    const __half* pDp = d_Dph + 4*q;
    const __half2 hz = __float2half2_rn(0.f);

    // B loop: Delta rows (~80 rows -> <=25 iters; small values, single promote)
    {
        __half2 c0 = hz, c1 = hz;
        for (int i = s; i < Bc; i += 4){
            int r = Bl[i] * NN;
            uint2 uv = *reinterpret_cast<const uint2*>(pDl + r);
            c0 = __hadd2(c0, *reinterpret_cast<__half2*>(&uv.x));
            c1 = __hadd2(c1, *reinterpret_cast<__half2*>(&uv.y));
        }
        float2 f0 = __half22float2(c0), f1 = __half22float2(c1);
        sB4[s][q] = make_float4(f0.x, f0.y, f1.x, f1.y);
    }

    // C loop: Dp rows (~160 rows -> <=40 iters), chunked fp32 promotion
    {
        float4 aX = make_float4(0.f,0.f,0.f,0.f);
        for (int i0 = s; i0 < Cc; i0 += 32){
            int lim = min(i0 + 32, Cc);
            __half2 d0 = hz, d1 = hz;
#pragma unroll 8
            for (int i = i0; i < lim; i += 4){
                int r = Cl[i] * NN;
                uint2 uv = *reinterpret_cast<const uint2*>(pDp + r);
                d0 = __hadd2(d0, *reinterpret_cast<__half2*>(&uv.x));
                d1 = __hadd2(d1, *reinterpret_cast<__half2*>(&uv.y));
            }
            float2 f0 = __half22float2(d0), f1 = __half22float2(d1);
            aX.x += f0.x; aX.y += f0.y; aX.z += f1.x; aX.w += f1.y;
        }
        sX4[s][q] = aX;
    }

    // sum_{a in B} x_a (fp32 exact): GG = ||sum||^2 = beta^T G beta
    {
        int dd = t & 63, g5 = t >> 6;   // 5 row-slices of 64 dims
        float sacc = 0.f;
        for (int i = g5; i < Bc; i += 5) sacc += x[Bl[i]*DD + dd];
        zp[t] = sacc;
    }
    __syncthreads();

    // Per-column totals (thread t = column t)
    const float* fB = reinterpret_cast<const float*>(sB4);
    const float* fX = reinterpret_cast<const float*>(sX4);
    float colB = fB[t] + fB[NN+t] + fB[2*NN+t] + fB[3*NN+t];
    float colX = fX[t] + fX[NN+t] + fX[2*NN+t] + fX[3*NN+t];

    float z2p = 0.f;
    if (t < 64){
        float z = zp[t] + zp[64+t] + zp[128+t] + zp[192+t] + zp[256+t];
        z2p = z*z;
    }

    float myb = beta[t], myc = chi[t];
    float vBB  = myb * colB;                       // beta^T Delta beta
    float vBX  = myc * colB;                       // chi^T Delta beta
    float vXX  = myc * colX;                       // chi^T Dp chi
    float vLin = (t < Bc) ? d_RD[Bl[t]] : 0.f;     // beta^T RDelta
    float vQ   = (t < Bc) ? d_qd[Bl[t]] : 0.f;     // X1 . sum_B x

    float r0 = warpRed(vBB), r1 = warpRed(z2p), r2 = warpRed(vBX),
          r3 = warpRed(vXX), r4 = warpRed(vLin), r5 = warpRed(vQ),
          r6 = warpRed(d_rowC[t]),                 // -> C_Dp
          r7 = warpRed(d_sn[t]),                   // -> S1
          r8 = warpRed(d_qd[t]);                   // -> ||X1||^2
    if (l == 0){ red[0][w]=r0; red[1][w]=r1; red[2][w]=r2;
                 red[3][w]=r3; red[4][w]=r4; red[5][w]=r5;
                 red[6][w]=r6; red[7][w]=r7; red[8][w]=r8; }
    __syncthreads();
    if (t == 0){
        float BB=0.f, GG=0.f, BX=0.f, XX=0.f, LIN=0.f, QS=0.f,
              CDP=0.f, S1=0.f, X1SQ=0.f;
#pragma unroll
        for (int i = 0; i < 10; i++){
            BB += red[0][i]; GG += red[1][i]; BX += red[2][i];
            XX += red[3][i]; LIN += red[4][i]; QS += red[5][i];
            CDP += red[6][i]; S1 += red[7][i]; X1SQ += red[8][i];
        }
        const float M = 51040.f;                    // 320*319/2
        float Sv  = CDP + LIN + BB - 2.f*BX - XX;
        float Z2  = X1SQ - 4.f*QS + 4.f*GG;         // ||X1 - 2 sum_B x||^2
        float Sv2 = 320.f * S1 - Z2;
        out[p] = (Sv2 - Sv*Sv/M) / (M - 1.f);
    }
}

extern "C" void kernel_launch(void* const* d_in, const int* in_sizes, int n_in,
                              void* d_out, int out_size){
    const float* data  = (const float*)d_in[0];
    const int*   ptype = (const int*)d_in[3];
    const int*   perms = (const int*)d_in[4];
    float* out = (float*)d_out;
    k_pre <<<NN,   NN>>>(data);
    k_main<<<1001, NN>>>(data, ptype, perms, out);
}

// round 8
// speedup vs baseline: 1.1393x; 1.0666x over previous
#include <cuda_runtime.h>
#include <cuda_fp16.h>

#define NN 320
#define DD 64
#define PB 7
#define NBLK 143   // 143*7 = 1001 datasets exactly

// Precomputed, perm-independent state.
__device__ __align__(16) __half2 d_PD[NN*NN]; // (Delta, Dp) packed per element
__device__ float d_RD[NN];      // row sums of Delta (fp32)
__device__ float d_rowC[NN];    // per-row sum of Dp over b>a (fp32)
__device__ float d_sn[NN];      // squared norms
__device__ float d_qd[NN];      // X1 . x_a = row sum of Gram

__device__ __forceinline__ float warpRed(float v){
#pragma unroll
    for (int o = 16; o > 0; o >>= 1) v += __shfl_down_sync(0xffffffffu, v, o);
    return v;
}
__device__ __forceinline__ __half2 u2h(unsigned u){
    return *reinterpret_cast<__half2*>(&u);
}

// Fused precompute: one block per row a, thread = column b.
__global__ void __launch_bounds__(NN) k_pre(const float* __restrict__ x){
    __shared__ float xa[DD];
    __shared__ float sa_sh;
    __shared__ float red[3][10];
    int a = blockIdx.x, b = threadIdx.x;
    if (b < DD) xa[b] = x[a*DD + b];
    __syncthreads();
    const float4* xb = reinterpret_cast<const float4*>(x + b*DD);
    float g = 0.f, nb = 0.f;
#pragma unroll
    for (int i = 0; i < DD/4; i++){
        float4 v = xb[i];
        g  += xa[4*i]*v.x + xa[4*i+1]*v.y + xa[4*i+2]*v.z + xa[4*i+3]*v.w;
        nb += v.x*v.x + v.y*v.y + v.z*v.z + v.w*v.w;
    }
    if (b == a){ sa_sh = nb; d_sn[a] = nb; }
    __syncthreads();
    float sa = sa_sh;
    float dp = sqrtf(fmaxf(sa + nb - 2.f*g, 0.f));
    float dm = sqrtf(fmaxf(sa + nb + 2.f*g, 0.f));
    float dl = dm - dp;
    d_PD[a*NN + b] = __floats2half2_rn(dl, dp);

    int w = b >> 5, l = b & 31;
    float v0 = warpRed(dl);
    float v1 = warpRed(b > a ? dp : 0.f);
    float v2 = warpRed(g);
    if (l == 0){ red[0][w] = v0; red[1][w] = v1; red[2][w] = v2; }
    __syncthreads();
    if (b == 0){
        float s0 = 0.f, s1 = 0.f, s2 = 0.f;
#pragma unroll
        for (int i = 0; i < 10; i++){ s0 += red[0][i]; s1 += red[1][i]; s2 += red[2][i]; }
        d_RD[a]   = s0;   // row sum of Delta
        d_rowC[a] = s1;   // row sum of Dp over b>a
        d_qd[a]   = s2;   // X1 . x_a
    }
}

// Main: one block per 7 datasets. Dense mask-streaming: no index lists.
// 320 threads = 4 row-slices x 80 quad-columns over the (Delta,Dp) matrix.
__global__ void __launch_bounds__(NN) k_main(const float* __restrict__ x,
                                             const int* __restrict__ ptype,
                                             const int* __restrict__ perms,
                                             float* __restrict__ out){
    __shared__ __align__(16) __half2 wts[NN][8];   // (beta, chi) per (index, perm); col 7 pad
    __shared__ __align__(16) float  betaF[NN][8];  // beta as fp32; col 7 pad
    __shared__ float sZp[5][PB][DD];               // s-vector slice partials
    __shared__ float red[PB*5+3][10];
    __shared__ float red2[PB][2];

    int t = threadIdx.x, bid = blockIdx.x;
    int w = t >> 5, l = t & 31;
    int fn = (ptype[t] == 0);

    // Build masks: thread t scatters to its image index a (bijection => full coverage).
#pragma unroll
    for (int pp = 0; pp < PB; pp++){
        int pi = bid*PB + pp;                 // dataset 0 = identity
        int a  = (pi == 0) ? t : perms[(pi-1)*NN + t];
        int fa = (ptype[a] == 0);
        int u  = (a != t) && fn && fa;
        wts[a][pp]   = __floats2half2_rn((float)u, (float)fn);
        betaF[a][pp] = (float)u;
    }
    __syncthreads();

    // ---- Dense stream: rows a = sl + 4*i, thread covers 4 columns 4g..4g+3 ----
    int g = t % 80, sl = t / 80;
    const __half2* rp = d_PD + (size_t)sl*NN + 4*g;
    const uint4*  wr = reinterpret_cast<const uint4*>(&wts[sl][0]);  // 2 uint4/row

    float fB_[PB][4], fX_[PB][4];
#pragma unroll
    for (int p = 0; p < PB; p++)
#pragma unroll
        for (int c = 0; c < 4; c++){ fB_[p][c] = 0.f; fX_[p][c] = 0.f; }

    int i = 0;
#pragma unroll
    for (int ch = 0; ch < 3; ch++){
        int lim = (ch == 0) ? 27 : (ch == 1) ? 54 : 80;
        __half2 acc[PB][4];
        const __half2 hz = __float2half2_rn(0.f);
#pragma unroll
        for (int p = 0; p < PB; p++)
#pragma unroll
            for (int c = 0; c < 4; c++) acc[p][c] = hz;
        for (; i < lim; i++){
            uint4 v4 = *reinterpret_cast<const uint4*>(rp);
            uint4 w0 = wr[0];
            uint4 w1 = wr[1];
            __half2 val[4] = { u2h(v4.x), u2h(v4.y), u2h(v4.z), u2h(v4.w) };
            __half2 wp[PB] = { u2h(w0.x), u2h(w0.y), u2h(w0.z), u2h(w0.w),
                               u2h(w1.x), u2h(w1.y), u2h(w1.z) };
#pragma unroll
            for (int p = 0; p < PB; p++)
#pragma unroll
                for (int c = 0; c < 4; c++)
                    acc[p][c] = __hfma2(val[c], wp[p], acc[p][c]);
            rp += 4*NN;   // next row in this slice
            wr += 8;      // 4 rows * 2 uint4
        }
#pragma unroll
        for (int p = 0; p < PB; p++)
#pragma unroll
            for (int c = 0; c < 4; c++){
                float2 f = __half22float2(acc[p][c]);
                fB_[p][c] += f.x;   // beta-weighted Delta col partial
                fX_[p][c] += f.y;   // chi-weighted Dp col partial
            }
    }

    // ---- Per-thread column-weighted partials (linear => no cross-slice combine) ----
    float bb[PB], bx[PB], xx[PB];
#pragma unroll
    for (int p = 0; p < PB; p++){ bb[p] = 0.f; bx[p] = 0.f; xx[p] = 0.f; }
#pragma unroll
    for (int c = 0; c < 4; c++){
        int col = 4*g + c;
#pragma unroll
        for (int p = 0; p < PB; p++){
            float2 wv = __half22float2(wts[col][p]);   // (beta, chi) of column
            bb[p] = fmaf(wv.x, fB_[p][c], bb[p]);
            bx[p] = fmaf(wv.y, fB_[p][c], bx[p]);
            xx[p] = fmaf(wv.y, fX_[p][c], xx[p]);
        }
    }

    // ---- E1 reductions: per-perm bb/bx/xx/lin/qs + 3 perm-independent scalars ----
    float rdv = d_RD[t], qdv = d_qd[t];
#pragma unroll
    for (int p = 0; p < PB; p++){
        float b  = betaF[t][p];
        float r0 = warpRed(bb[p]);
        float r1 = warpRed(bx[p]);
        float r2 = warpRed(xx[p]);
        float r3 = warpRed(b*rdv);   // LIN = beta . RD
        float r4 = warpRed(b*qdv);   // QS  = beta . qd
        if (l == 0){
            red[p*5+0][w] = r0; red[p*5+1][w] = r1; red[p*5+2][w] = r2;
            red[p*5+3][w] = r3; red[p*5+4][w] = r4;
        }
    }
    {
        float rc = warpRed(d_rowC[t]);   // -> C_Dp
        float rs = warpRed(d_sn[t]);     // -> S1
        float rq = warpRed(qdv);         // -> ||X1||^2
        if (l == 0){ red[PB*5+0][w] = rc; red[PB*5+1][w] = rs; red[PB*5+2][w] = rq; }
    }

    // ---- s_p = sum_a beta_p[a] * x[a,:]  (fp32 exact), 5 row-slices x 64 dims ----
    {
        int d = t & 63, g5 = t >> 6;
        float sacc[PB];
#pragma unroll
        for (int p = 0; p < PB; p++) sacc[p] = 0.f;
        const float*  xp = x + (size_t)g5*DD + d;
        const float4* bp = reinterpret_cast<const float4*>(&betaF[g5][0]);
#pragma unroll 4
        for (int i2 = 0; i2 < 64; i2++){
            float xv = *xp;
            float4 b0 = bp[0], b1 = bp[1];
            sacc[0] = fmaf(b0.x, xv, sacc[0]);
            sacc[1] = fmaf(b0.y, xv, sacc[1]);
            sacc[2] = fmaf(b0.z, xv, sacc[2]);
            sacc[3] = fmaf(b0.w, xv, sacc[3]);
            sacc[4] = fmaf(b1.x, xv, sacc[4]);
            sacc[5] = fmaf(b1.y, xv, sacc[5]);
            sacc[6] = fmaf(b1.z, xv, sacc[6]);
            xp += 5*DD;   // rows stride 5
            bp += 10;     // 5 rows * 2 float4
        }
#pragma unroll
        for (int p = 0; p < PB; p++) sZp[g5][p][d] = sacc[p];
    }
    __syncthreads();

    // ---- E2: GG_p = ||s_p||^2 ----
    if (t < DD){
#pragma unroll
        for (int p = 0; p < PB; p++){
            float s = sZp[0][p][t] + sZp[1][p][t] + sZp[2][p][t]
                    + sZp[3][p][t] + sZp[4][p][t];
            float r = warpRed(s*s);
            if (l == 0) red2[p][w] = r;   // warps 0,1
        }
    }
    __syncthreads();

    // ---- Final combine: one thread per perm ----
    if (t < PB){
        float BB=0.f, BX=0.f, XX=0.f, LIN=0.f, QS=0.f, CDP=0.f, S1=0.f, X1SQ=0.f;
#pragma unroll
        for (int i3 = 0; i3 < 10; i3++){
            BB  += red[t*5+0][i3]; BX += red[t*5+1][i3]; XX += red[t*5+2][i3];
            LIN += red[t*5+3][i3]; QS += red[t*5+4][i3];
            CDP += red[PB*5+0][i3]; S1 += red[PB*5+1][i3]; X1SQ += red[PB*5+2][i3];
        }
        float GG = red2[t][0] + red2[t][1];
        const float M = 51040.f;                    // 320*319/2
        float Sv  = CDP + LIN + BB - 2.f*BX - XX;
        float Z2  = X1SQ - 4.f*QS + 4.f*GG;         // ||X1 - 2 sum_B x||^2
        float Sv2 = 320.f * S1 - Z2;
        out[bid*PB + t] = (Sv2 - Sv*Sv/M) / (M - 1.f);
    }
}

extern "C" void kernel_launch(void* const* d_in, const int* in_sizes, int n_in,
                              void* d_out, int out_size){
    const float* data  = (const float*)d_in[0];
    const int*   ptype = (const int*)d_in[3];
    const int*   perms = (const int*)d_in[4];
    float* out = (float*)d_out;
    k_pre <<<NN,   NN>>>(data);
    k_main<<<NBLK, NN>>>(data, ptype, perms, out);
}